// round 1
// baseline (speedup 1.0000x reference)
#include <cuda_runtime.h>
#include <stdint.h>

// ---- JAX threefry mode: 1 = jax_threefry_partitionable (default in jax >= 0.4.36)
#define PARTITIONABLE 1

#define ND   10000
#define NT   20000
#define DIM  64
#define SS   16
#define EMAX 1000000
#define UNITS (ND*SS)

typedef unsigned int u32;
typedef unsigned long long u64;

// ---------------------------------------------------------------- threefry2x32
__host__ __device__ __forceinline__ void tf_round(u32& x0, u32& x1, int r) {
    x0 += x1;
    x1 = (x1 << r) | (x1 >> (32 - r));
    x1 ^= x0;
}
__host__ __device__ __forceinline__ void threefry(u32 k0, u32 k1, u32 x0, u32 x1,
                                                  u32& o0, u32& o1) {
    u32 ks2 = k0 ^ k1 ^ 0x1BD11BDAu;
    x0 += k0; x1 += k1;
    tf_round(x0,x1,13); tf_round(x0,x1,15); tf_round(x0,x1,26); tf_round(x0,x1,6);
    x0 += k1; x1 += ks2 + 1u;
    tf_round(x0,x1,17); tf_round(x0,x1,29); tf_round(x0,x1,16); tf_round(x0,x1,24);
    x0 += ks2; x1 += k0 + 2u;
    tf_round(x0,x1,13); tf_round(x0,x1,15); tf_round(x0,x1,26); tf_round(x0,x1,6);
    x0 += k0; x1 += k1 + 3u;
    tf_round(x0,x1,17); tf_round(x0,x1,29); tf_round(x0,x1,16); tf_round(x0,x1,24);
    x0 += k1; x1 += ks2 + 4u;
    tf_round(x0,x1,13); tf_round(x0,x1,15); tf_round(x0,x1,26); tf_round(x0,x1,6);
    x0 += ks2; x1 += k0 + 5u;
    o0 = x0; o1 = x1;
}

// random_bits(key, 32, (n,)) element i, matching jax in either threefry mode.
__device__ __forceinline__ u32 rbits_stream(u32 kx, u32 ky, int i, int n) {
#if PARTITIONABLE
    u32 a, b; threefry(kx, ky, 0u, (u32)i, a, b);
    return a ^ b;
#else
    int half = n >> 1;            // n is even for all uses here
    u32 a, b;
    if (i < half) { threefry(kx, ky, (u32)i, (u32)(i + half), a, b); return a; }
    threefry(kx, ky, (u32)(i - half), (u32)i, a, b); return b;
#endif
}

// ---------------------------------------------------------------- scratch
__device__ int   g_deg[ND];
__device__ int   g_cursor[ND];
__device__ int   g_off[ND];
__device__ int   g_csr[EMAX];
__device__ u32   g_rk[EMAX];          // (bits >> 9): 23-bit uniform mantissa key
__device__ int   g_sel[UNITS];        // rank-ordered selected edge ids
__device__ int   g_selcnt[ND];
__device__ int   g_seltail[UNITS];
__device__ float g_selscore[UNITS];
__device__ float g_neigh[ND*DIM];
__device__ float g_y[ND*DIM];
__device__ float g_psum[(ND/4)*DIM];
__device__ float g_psq[(ND/4)*DIM];
__device__ float g_mean[DIM];
__device__ float g_rstd[DIM];
__device__ float g_w2s[DIM];
__device__ float g_b2s;

// ---------------------------------------------------------------- kernels
__global__ void zero_kernel() {
    int i = blockIdx.x * blockDim.x + threadIdx.x;
    if (i < ND) { g_deg[i] = 0; g_cursor[i] = 0; }
}

__global__ void w2s_kernel(const float* __restrict__ W2, const float* __restrict__ b2) {
    int i = threadIdx.x;           // 64 threads
    float s = 0.f;
    for (int j = 0; j < DIM; j++) s += W2[i*DIM + j];
    g_w2s[i] = s;
    if (i == 0) {
        float t = 0.f;
        for (int j = 0; j < DIM; j++) t += b2[j];
        g_b2s = t;
    }
}

// degree histogram + per-edge uniform rank key
__global__ void hist_kernel(const int* __restrict__ DKG, int E, u32 k1x, u32 k1y) {
    int e = blockIdx.x * blockDim.x + threadIdx.x;
    if (e >= E) return;
    int h = DKG[3*e];
    atomicAdd(&g_deg[h], 1);
    u32 bits = rbits_stream(k1x, k1y, e, E);
    g_rk[e] = bits >> 9;           // float order == (bits>>9) order
}

// exclusive scan of deg -> off (single block)
__global__ void scan_kernel() {
    __shared__ int sh[1024];
    __shared__ int carry_s;
    if (threadIdx.x == 0) carry_s = 0;
    __syncthreads();
    for (int base = 0; base < ND; base += 1024) {
        int i = base + threadIdx.x;
        int v = (i < ND) ? g_deg[i] : 0;
        sh[threadIdx.x] = v;
        __syncthreads();
        for (int ofs = 1; ofs < 1024; ofs <<= 1) {
            int t = (threadIdx.x >= ofs) ? sh[threadIdx.x - ofs] : 0;
            __syncthreads();
            sh[threadIdx.x] += t;
            __syncthreads();
        }
        if (i < ND) g_off[i] = carry_s + sh[threadIdx.x] - v;
        __syncthreads();
        if (threadIdx.x == 0) carry_s += sh[1023];
        __syncthreads();
    }
}

__global__ void scatter_kernel(const int* __restrict__ DKG, int E) {
    int e = blockIdx.x * blockDim.x + threadIdx.x;
    if (e >= E) return;
    int h = DKG[3*e];
    int pos = g_off[h] + atomicAdd(&g_cursor[h], 1);
    g_csr[pos] = e;
}

// per-segment: find 16 smallest (r, edge) keys; write them rank-ordered.
__global__ void __launch_bounds__(128) select_kernel() {
    int d = blockIdx.x;
    int off = g_off[d];
    int degd = g_deg[d];
    if (threadIdx.x == 0) g_selcnt[d] = (degd < SS) ? degd : SS;
    if (degd == 0) return;
    __shared__ u64 keys[1024];
    if (degd <= 1024) {
        for (int t = threadIdx.x; t < degd; t += blockDim.x) {
            int e = g_csr[off + t];
            keys[t] = (((u64)g_rk[e]) << 20) | (u32)e;   // e < 2^20
        }
        __syncthreads();
        for (int t = threadIdx.x; t < degd; t += blockDim.x) {
            u64 k = keys[t];
            int rank = 0;
            for (int j = 0; j < degd; j++) rank += (keys[j] < k);
            if (rank < SS) g_sel[d*SS + rank] = (int)(k & 0xFFFFFu);
        }
    } else {   // never expected for this input; correctness fallback
        for (int t = threadIdx.x; t < degd; t += blockDim.x) {
            int e = g_csr[off + t];
            u64 k = (((u64)g_rk[e]) << 20) | (u32)e;
            int rank = 0;
            for (int j = 0; j < degd; j++) {
                int e2 = g_csr[off + j];
                u64 k2 = (((u64)g_rk[e2]) << 20) | (u32)e2;
                rank += (k2 < k);
            }
            if (rank < SS) g_sel[d*SS + rank] = e;
        }
    }
}

// MLP score only for selected edges (warp per unit, 4 units/warp).
__global__ void __launch_bounds__(256) score_kernel(const int* __restrict__ DKG,
                                                    const float* __restrict__ drug_emb,
                                                    const float* __restrict__ rel_emb,
                                                    const float* __restrict__ W1,
                                                    const float* __restrict__ b1) {
    __shared__ float W1s[DIM*DIM];
    __shared__ float b1s[DIM];
    __shared__ float w2ss[DIM];
    int tid = threadIdx.x;
    for (int i = tid; i < DIM*DIM; i += 256) W1s[i] = W1[i];
    if (tid < DIM) { b1s[tid] = b1[tid]; w2ss[tid] = g_w2s[tid]; }
    __syncthreads();
    int lane = tid & 31, w = tid >> 5;
    int base = (blockIdx.x * 8 + w) * 4;
    for (int q = 0; q < 4; q++) {
        int u = base + q;                      // < UNITS by construction
        int d = u >> 4, k = u & 15;
        if (k >= g_selcnt[d]) continue;        // uniform across warp
        int e = g_sel[u];
        int tail = DKG[3*e + 1];
        int rel  = DKG[3*e + 2];
        float h0 = drug_emb[d*DIM + lane]      * rel_emb[rel*DIM + lane];
        float h1 = drug_emb[d*DIM + 32 + lane] * rel_emb[rel*DIM + 32 + lane];
        float a0 = b1s[lane], a1 = b1s[lane + 32];
        #pragma unroll
        for (int i = 0; i < 32; i++) {
            float v = __shfl_sync(0xffffffffu, h0, i);
            a0 = fmaf(v, W1s[i*DIM + lane], a0);
            a1 = fmaf(v, W1s[i*DIM + lane + 32], a1);
        }
        #pragma unroll
        for (int i = 0; i < 32; i++) {
            float v = __shfl_sync(0xffffffffu, h1, i);
            a0 = fmaf(v, W1s[(i+32)*DIM + lane], a0);
            a1 = fmaf(v, W1s[(i+32)*DIM + lane + 32], a1);
        }
        float s0 = 1.f / (1.f + __expf(-a0));
        float s1 = 1.f / (1.f + __expf(-a1));
        float p = s0 * w2ss[lane] + s1 * w2ss[lane + 32];
        #pragma unroll
        for (int o = 16; o; o >>= 1) p += __shfl_xor_sync(0xffffffffu, p, o);
        if (lane == 0) {
            g_selscore[u] = p + g_b2s;
            g_seltail[u] = tail;
        }
    }
}

// neighbor aggregation (deterministic order), incl. with-replacement extras.
__global__ void __launch_bounds__(64) agg_kernel(const float* __restrict__ tail_emb,
                                                 u32 kLx, u32 kLy) {
    int d = blockIdx.x, j = threadIdx.x;
    int cnt = g_selcnt[d];
    int degd = g_deg[d];
    float acc = 0.f;
    for (int k = 0; k < cnt; k++) {
        float sc = g_selscore[d*SS + k];
        int t = g_seltail[d*SS + k];
        acc = fmaf(sc, tail_emb[t*DIM + j], acc);
    }
    if (degd > 0 && degd < SS) {
        for (int s = 0; s < SS - degd; s++) {
            u32 bits = rbits_stream(kLx, kLy, d*SS + s, UNITS);
            int uu = (int)(bits % 2147483647u);     // randint(0, INT32_MAX)
            int idx = uu % degd;
            acc = fmaf(g_selscore[d*SS + idx],
                       tail_emb[g_seltail[d*SS + idx]*DIM + j], acc);
        }
    }
    g_neigh[d*DIM + j] = acc;
}

// y = [drug_emb, neigh] @ Wc + bc ; per-block column partial sums/sumsq.
__global__ void __launch_bounds__(256) y_kernel(const float* __restrict__ drug_emb,
                                                const float* __restrict__ Wc,
                                                const float* __restrict__ bc) {
    __shared__ float Wcs[2*DIM*DIM];       // 32 KB
    for (int i = threadIdx.x; i < 2*DIM*DIM; i += 256) Wcs[i] = Wc[i];
    __syncthreads();
    int row = blockIdx.x * 4 + (threadIdx.x >> 6);
    int o = threadIdx.x & 63;
    const float* de = drug_emb + row*DIM;
    const float* ne = g_neigh + row*DIM;
    float acc = bc[o];
    #pragma unroll
    for (int i = 0; i < DIM; i++) acc = fmaf(de[i], Wcs[i*DIM + o], acc);
    #pragma unroll
    for (int i = 0; i < DIM; i++) acc = fmaf(ne[i], Wcs[(DIM+i)*DIM + o], acc);
    g_y[row*DIM + o] = acc;
    __shared__ float red[256];
    red[threadIdx.x] = acc;
    __syncthreads();
    if (threadIdx.x < 64)
        g_psum[blockIdx.x*DIM + o] = red[o] + red[64+o] + red[128+o] + red[192+o];
    __syncthreads();
    red[threadIdx.x] = acc * acc;
    __syncthreads();
    if (threadIdx.x < 64)
        g_psq[blockIdx.x*DIM + o] = red[o] + red[64+o] + red[128+o] + red[192+o];
}

__global__ void reduce_kernel() {
    __shared__ float ss[256], qq[256];
    int c = threadIdx.x & 63, part = threadIdx.x >> 6;
    float s = 0.f, q = 0.f;
    for (int b = part; b < ND/4; b += 4) { s += g_psum[b*DIM + c]; q += g_psq[b*DIM + c]; }
    ss[threadIdx.x] = s; qq[threadIdx.x] = q;
    __syncthreads();
    if (threadIdx.x < 64) {
        float S = ss[c] + ss[64+c] + ss[128+c] + ss[192+c];
        float Q = qq[c] + qq[64+c] + qq[128+c] + qq[192+c];
        float mean = S / (float)ND;
        float var = Q / (float)ND - mean * mean;
        g_mean[c] = mean;
        g_rstd[c] = rsqrtf(var + 1e-5f);
    }
}

__global__ void norm_kernel(float* __restrict__ out,
                            const float* __restrict__ gamma,
                            const float* __restrict__ beta) {
    int idx = blockIdx.x * blockDim.x + threadIdx.x;
    if (idx >= ND*DIM) return;
    int o = idx & 63;
    out[idx] = gamma[o] * (g_y[idx] - g_mean[o]) * g_rstd[o] + beta[o];
}

// ---------------------------------------------------------------- host
static void compute_keys(u32& k1x, u32& k1y, u32& kLx, u32& kLy) {
#if PARTITIONABLE
    u32 a, b, c, d, e, f;
    threefry(0u, 42u, 0u, 0u, a, b);   // k1 = split(key(42))[0]
    k1x = a; k1y = b;
    threefry(0u, 42u, 0u, 1u, c, d);   // k2 = split(key(42))[1]
    threefry(c, d, 0u, 1u, e, f);      // split(k2)[1]  (lower_bits key in randint)
    kLx = e; kLy = f;
#else
    u32 a0, b0, a1, b1;
    threefry(0u, 42u, 0u, 2u, a0, b0);
    threefry(0u, 42u, 1u, 3u, a1, b1);
    k1x = a0; k1y = a1;                 // k1 = (a0, a1); k2 = (b0, b1)
    u32 c0, d0, c1, d1;
    threefry(b0, b1, 0u, 2u, c0, d0);
    threefry(b0, b1, 1u, 3u, c1, d1);
    kLx = d0; kLy = d1;                 // split(k2)[1]
#endif
}

extern "C" void kernel_launch(void* const* d_in, const int* in_sizes, int n_in,
                              void* d_out, int out_size) {
    const float* HF       = (const float*)d_in[0];
    const float* X        = (const float*)d_in[1];
    const float* drug_emb = (const float*)d_in[2];
    const float* rel_emb  = (const float*)d_in[3];
    const float* tail_emb = (const float*)d_in[4];
    const float* W1       = (const float*)d_in[5];
    const float* b1       = (const float*)d_in[6];
    const float* W2       = (const float*)d_in[7];
    const float* b2       = (const float*)d_in[8];
    const float* Wc       = (const float*)d_in[9];
    const float* bc       = (const float*)d_in[10];
    const float* gamma    = (const float*)d_in[11];
    const float* beta     = (const float*)d_in[12];
    const int*   DKG      = (const int*)d_in[13];
    int E    = in_sizes[13] / 3;
    int hf_n = in_sizes[0];
    int x_n  = in_sizes[1];
    float* out = (float*)d_out;

    u32 k1x, k1y, kLx, kLy;
    compute_keys(k1x, k1y, kLx, kLy);

    // passthrough outputs: [HFEmbeding | out | X]
    cudaMemcpyAsync(out, HF, (size_t)hf_n * sizeof(float), cudaMemcpyDeviceToDevice, 0);
    cudaMemcpyAsync(out + hf_n + ND*DIM, X, (size_t)x_n * sizeof(float),
                    cudaMemcpyDeviceToDevice, 0);

    zero_kernel<<<(ND + 255)/256, 256>>>();
    w2s_kernel<<<1, 64>>>(W2, b2);
    hist_kernel<<<(E + 255)/256, 256>>>(DKG, E, k1x, k1y);
    scan_kernel<<<1, 1024>>>();
    scatter_kernel<<<(E + 255)/256, 256>>>(DKG, E);
    select_kernel<<<ND, 128>>>();
    score_kernel<<<UNITS/32, 256>>>(DKG, drug_emb, rel_emb, W1, b1);
    agg_kernel<<<ND, 64>>>(tail_emb, kLx, kLy);
    y_kernel<<<ND/4, 256>>>(drug_emb, Wc, bc);
    reduce_kernel<<<1, 256>>>();
    norm_kernel<<<(ND*DIM + 255)/256, 256>>>(out + hf_n, gamma, beta);
}

// round 2
// speedup vs baseline: 1.0805x; 1.0805x over previous
#include <cuda_runtime.h>
#include <stdint.h>

#define PARTITIONABLE 1

#define ND   10000
#define DIM  64
#define SS   16
#define EMAX 1000000
#define UNITS (ND*SS)
#define NBLK 296
#define NTHR 256
#define NWARP (NBLK*8)
#define CHUNK 34            // ceil(ND/NBLK)

typedef unsigned int u32;
typedef unsigned long long u64;

// ---------------------------------------------------------------- threefry2x32
__device__ __forceinline__ void tf_round(u32& x0, u32& x1, int r) {
    x0 += x1;
    x1 = (x1 << r) | (x1 >> (32 - r));
    x1 ^= x0;
}
__host__ __device__ __forceinline__ void threefry(u32 k0, u32 k1, u32 x0, u32 x1,
                                                  u32& o0, u32& o1) {
#ifdef __CUDA_ARCH__
#define TFR(a,b,r) { a += b; b = (b<<r)|(b>>(32-r)); b ^= a; }
#else
#define TFR(a,b,r) { a += b; b = (b<<r)|(b>>(32-r)); b ^= a; }
#endif
    u32 ks2 = k0 ^ k1 ^ 0x1BD11BDAu;
    x0 += k0; x1 += k1;
    TFR(x0,x1,13); TFR(x0,x1,15); TFR(x0,x1,26); TFR(x0,x1,6);
    x0 += k1; x1 += ks2 + 1u;
    TFR(x0,x1,17); TFR(x0,x1,29); TFR(x0,x1,16); TFR(x0,x1,24);
    x0 += ks2; x1 += k0 + 2u;
    TFR(x0,x1,13); TFR(x0,x1,15); TFR(x0,x1,26); TFR(x0,x1,6);
    x0 += k0; x1 += k1 + 3u;
    TFR(x0,x1,17); TFR(x0,x1,29); TFR(x0,x1,16); TFR(x0,x1,24);
    x0 += k1; x1 += ks2 + 4u;
    TFR(x0,x1,13); TFR(x0,x1,15); TFR(x0,x1,26); TFR(x0,x1,6);
    x0 += ks2; x1 += k0 + 5u;
    o0 = x0; o1 = x1;
#undef TFR
}

__device__ __forceinline__ u32 rbits_stream(u32 kx, u32 ky, int i) {
    // PARTITIONABLE mode: counter = flat iota, out = o0 ^ o1
    u32 a, b; threefry(kx, ky, 0u, (u32)i, a, b);
    return a ^ b;
}

// ---------------------------------------------------------------- scratch
__device__ int   g_deg[ND];
__device__ int   g_cursor[ND];
__device__ int   g_off[ND];
__device__ u64   g_key[EMAX];
__device__ int   g_bsum[NBLK];
__device__ int   g_boff[NBLK];
__device__ int   g_sel[UNITS];
__device__ int   g_selcnt[ND];
__device__ int   g_seltail[UNITS];
__device__ float g_selscore[UNITS];
__device__ float g_neigh[ND*DIM];
__device__ float g_y[ND*DIM];
__device__ float g_psum[NBLK*DIM];
__device__ float g_psq[NBLK*DIM];
__device__ float g_mean[DIM];
__device__ float g_rstd[DIM];
__device__ float g_w2s[DIM];
__device__ float g_b2s;
__device__ u32   g_bar_count;
__device__ u32   g_bar_gen;

// ---------------------------------------------------------------- init kernel
__global__ void init_kernel(const float* __restrict__ W2, const float* __restrict__ b2) {
    int i = blockIdx.x * blockDim.x + threadIdx.x;
    if (i < ND) { g_deg[i] = 0; g_cursor[i] = 0; }
    if (blockIdx.x == gridDim.x - 1) {
        int t = threadIdx.x;
        if (t == 0) { g_bar_count = 0; g_bar_gen = 0; }
        if (t < DIM) {
            float s = 0.f;
            for (int j = 0; j < DIM; j++) s += W2[t*DIM + j];
            g_w2s[t] = s;
        }
        if (t == DIM) {
            float s = 0.f;
            for (int j = 0; j < DIM; j++) s += b2[j];
            g_b2s = s;
        }
    }
}

// ---------------------------------------------------------------- f32x2 helpers
__device__ __forceinline__ u64 pack2(float lo, float hi) {
    u64 r;
    asm("mov.b64 %0, {%1, %2};" : "=l"(r) : "f"(lo), "f"(hi));
    return r;
}
__device__ __forceinline__ void unpack2(u64 v, float& lo, float& hi) {
    asm("mov.b64 {%0, %1}, %2;" : "=f"(lo), "=f"(hi) : "l"(v));
}
__device__ __forceinline__ void fma2(u64& acc, u64 a, u64 b) {
    asm("fma.rn.f32x2 %0, %1, %2, %0;" : "+l"(acc) : "l"(a), "l"(b));
}

// ---------------------------------------------------------------- mega kernel
__global__ void __launch_bounds__(NTHR, 2)
mega_kernel(const int* __restrict__ DKG,
            const float* __restrict__ drug_emb,
            const float* __restrict__ rel_emb,
            const float* __restrict__ tail_emb,
            const float* __restrict__ W1,
            const float* __restrict__ b1,
            const float* __restrict__ Wc,
            const float* __restrict__ bc,
            const float* __restrict__ gamma,
            const float* __restrict__ beta,
            float* __restrict__ out,
            int E, u32 k1x, u32 k1y, u32 kLx, u32 kLy) {
    __shared__ __align__(16) char sh_raw[34*1024];
    __shared__ u32 s_gen;

    const int tid  = threadIdx.x;
    const int bid  = blockIdx.x;
    const int gtid = bid * NTHR + tid;
    const int nth  = NBLK * NTHR;
    const int lane = tid & 31;
    const int wid  = tid >> 5;

    if (tid == 0) s_gen = 0;

    // -------- grid barrier --------
    auto gsync = [&]() {
        __syncthreads();
        if (tid == 0) {
            u32 target = s_gen + 1;
            __threadfence();
            u32 t = atomicAdd(&g_bar_count, 1u);
            if (t == (u32)NBLK - 1) {
                atomicExch(&g_bar_count, 0u);
                __threadfence();
                atomicExch(&g_bar_gen, target);
            } else {
                while (atomicAdd(&g_bar_gen, 0u) < target) { }
            }
            s_gen = target;
        }
        __syncthreads();
    };

    // ============ phase 1: degree histogram ============
    for (int e = gtid; e < E; e += nth) {
        atomicAdd(&g_deg[DKG[3*e]], 1);
    }
    gsync();

    // ============ phase 2: exclusive scan of deg -> off ============
    int* s_scan = (int*)sh_raw;            // 64 ints
    int* s_b    = (int*)(sh_raw + 1024);   // 512 ints
    const int d0 = bid * CHUNK;
    int myv = 0;
    if (tid < 64) s_scan[tid] = 0;
    __syncthreads();
    if (tid < CHUNK && d0 + tid < ND) { myv = g_deg[d0 + tid]; s_scan[tid] = myv; }
    __syncthreads();
    #pragma unroll
    for (int ofs = 1; ofs < 64; ofs <<= 1) {
        int v = (tid < 64 && tid >= ofs) ? s_scan[tid - ofs] : 0;
        __syncthreads();
        if (tid < 64) s_scan[tid] += v;
        __syncthreads();
    }
    if (tid == 0) g_bsum[bid] = s_scan[63];
    gsync();

    if (bid == 0) {
        s_b[tid]       = (tid < NBLK) ? g_bsum[tid] : 0;
        s_b[tid + 256] = (tid + 256 < NBLK) ? g_bsum[tid + 256] : 0;
        __syncthreads();
        #pragma unroll
        for (int ofs = 1; ofs < 512; ofs <<= 1) {
            int v0 = (tid >= ofs) ? s_b[tid - ofs] : 0;
            int v1 = (tid + 256 >= ofs) ? s_b[tid + 256 - ofs] : 0;
            __syncthreads();
            s_b[tid] += v0;
            s_b[tid + 256] += v1;
            __syncthreads();
        }
        if (tid < NBLK) g_boff[tid] = tid ? s_b[tid - 1] : 0;
        if (tid + 256 < NBLK) g_boff[tid + 256] = s_b[tid + 255];
    }
    gsync();

    if (tid < CHUNK && d0 + tid < ND)
        g_off[d0 + tid] = g_boff[bid] + s_scan[tid] - myv;
    gsync();

    // ============ phase 3: scatter keys into CSR ============
    for (int e = gtid; e < E; e += nth) {
        int h = DKG[3*e];
        u32 bits = rbits_stream(k1x, k1y, e);
        u64 key = (((u64)(bits >> 9)) << 20) | (u32)e;
        int pos = g_off[h] + atomicAdd(&g_cursor[h], 1);
        g_key[pos] = key;
    }
    gsync();

    // ============ phase 4: per-drug top-16 selection (warp per drug) ============
    {
        u64* wkeys = ((u64*)sh_raw) + (size_t)wid * 256;   // 8 warps * 256 u64 = 16KB
        int gw = bid * 8 + wid;
        for (int d = gw; d < ND; d += NWARP) {
            int off  = g_off[d];
            int degd = g_deg[d];
            if (lane == 0) g_selcnt[d] = (degd < SS) ? degd : SS;
            if (degd == 0) continue;
            if (degd <= 256) {
                for (int t = lane; t < degd; t += 32) wkeys[t] = g_key[off + t];
                __syncwarp();
                for (int t = lane; t < degd; t += 32) {
                    u64 k = wkeys[t];
                    int rank = 0;
                    for (int j = 0; j < degd; j++) rank += (wkeys[j] < k);
                    if (rank < SS) g_sel[d*SS + rank] = (int)(k & 0xFFFFFu);
                }
                __syncwarp();
            } else {
                for (int t = lane; t < degd; t += 32) {
                    u64 k = g_key[off + t];
                    int rank = 0;
                    for (int j = 0; j < degd; j++) rank += (g_key[off + j] < k);
                    if (rank < SS) g_sel[d*SS + rank] = (int)(k & 0xFFFFFu);
                }
            }
        }
    }
    gsync();

    // ============ phase 5: MLP score for selected edges ============
    {
        u64*   w1p  = (u64*)sh_raw;                       // 2048 * 8B = 16KB (packed float2)
        float* b1s  = (float*)(sh_raw + 16*1024);
        float* w2ss = (float*)(sh_raw + 16*1024 + 256);
        for (int i = tid; i < 64*32; i += NTHR) {
            int r = i >> 5, c = i & 31;
            w1p[i] = pack2(W1[r*DIM + c], W1[r*DIM + c + 32]);
        }
        if (tid < DIM) { b1s[tid] = b1[tid]; w2ss[tid] = g_w2s[tid]; }
        __syncthreads();
        float b2s = g_b2s;

        int gw = bid * 8 + wid;
        for (int u = gw; u < UNITS; u += NWARP) {
            int d = u >> 4, k = u & 15;
            if (k >= g_selcnt[d]) continue;   // warp-uniform
            int e = g_sel[u];
            int tail = DKG[3*e + 1];
            int rel  = DKG[3*e + 2];
            float h0 = drug_emb[d*DIM + lane]      * rel_emb[rel*DIM + lane];
            float h1 = drug_emb[d*DIM + 32 + lane] * rel_emb[rel*DIM + 32 + lane];
            u64 acc = pack2(b1s[lane], b1s[lane + 32]);
            #pragma unroll
            for (int i = 0; i < 32; i++) {
                float v = __shfl_sync(0xffffffffu, h0, i);
                fma2(acc, pack2(v, v), w1p[i*32 + lane]);
            }
            #pragma unroll
            for (int i = 0; i < 32; i++) {
                float v = __shfl_sync(0xffffffffu, h1, i);
                fma2(acc, pack2(v, v), w1p[(i + 32)*32 + lane]);
            }
            float a0, a1;
            unpack2(acc, a0, a1);
            float s0 = 1.f / (1.f + __expf(-a0));
            float s1 = 1.f / (1.f + __expf(-a1));
            float p = s0 * w2ss[lane] + s1 * w2ss[lane + 32];
            #pragma unroll
            for (int o = 16; o; o >>= 1) p += __shfl_xor_sync(0xffffffffu, p, o);
            if (lane == 0) {
                g_selscore[u] = p + b2s;
                g_seltail[u]  = tail;
            }
        }
    }
    gsync();

    // ============ phase 6: neighbor aggregation ============
    for (int t = gtid; t < ND*DIM; t += nth) {
        int d = t >> 6, j = t & 63;
        int cnt  = g_selcnt[d];
        int degd = g_deg[d];
        float acc = 0.f;
        for (int k = 0; k < cnt; k++) {
            acc = fmaf(g_selscore[d*SS + k], tail_emb[g_seltail[d*SS + k]*DIM + j], acc);
        }
        if (degd > 0 && degd < SS) {
            for (int s = 0; s < SS - degd; s++) {
                u32 bits = rbits_stream(kLx, kLy, d*SS + s);
                int uu = (int)(bits % 2147483647u);
                int idx = uu % degd;
                acc = fmaf(g_selscore[d*SS + idx],
                           tail_emb[g_seltail[d*SS + idx]*DIM + j], acc);
            }
        }
        g_neigh[t] = acc;
    }
    gsync();

    // ============ phase 7: y = [drug_emb, neigh] @ Wc + bc, partial BN stats ============
    {
        float* wcs = (float*)sh_raw;                 // 8192 floats = 32KB
        float* red = (float*)(sh_raw + 32*1024);     // 256 floats
        for (int i = tid; i < 2*DIM*DIM; i += NTHR) wcs[i] = Wc[i];
        __syncthreads();
        int sub = tid >> 6;
        int col = tid & 63;
        float accS = 0.f, accQ = 0.f;
        float bcc = bc[col];
        for (int r4 = bid; r4 < ND/4; r4 += NBLK) {
            int row = r4*4 + sub;
            const float* de = drug_emb + row*DIM;
            const float* ne = g_neigh + row*DIM;
            float acc = bcc;
            #pragma unroll
            for (int i = 0; i < DIM; i++) acc = fmaf(de[i], wcs[i*DIM + col], acc);
            #pragma unroll
            for (int i = 0; i < DIM; i++) acc = fmaf(ne[i], wcs[(DIM + i)*DIM + col], acc);
            g_y[row*DIM + col] = acc;
            accS += acc;
            accQ += acc * acc;
        }
        red[tid] = accS;
        __syncthreads();
        if (tid < 64) g_psum[bid*DIM + col] = red[col] + red[64+col] + red[128+col] + red[192+col];
        __syncthreads();
        red[tid] = accQ;
        __syncthreads();
        if (tid < 64) g_psq[bid*DIM + col] = red[col] + red[64+col] + red[128+col] + red[192+col];
    }
    gsync();

    // ============ phase 8: final BN stats (block 0) ============
    if (bid == 0) {
        float* ss = (float*)sh_raw;
        float* qq = (float*)(sh_raw + 1024);
        int col = tid & 63, part = tid >> 6;
        float s = 0.f, q = 0.f;
        for (int b = part; b < NBLK; b += 4) { s += g_psum[b*DIM + col]; q += g_psq[b*DIM + col]; }
        ss[tid] = s; qq[tid] = q;
        __syncthreads();
        if (tid < 64) {
            float S = ss[col] + ss[64+col] + ss[128+col] + ss[192+col];
            float Q = qq[col] + qq[64+col] + qq[128+col] + qq[192+col];
            float mean = S / (float)ND;
            float var  = Q / (float)ND - mean * mean;
            g_mean[col] = mean;
            g_rstd[col] = rsqrtf(var + 1e-5f);
        }
    }
    gsync();

    // ============ phase 9: normalize + write out ============
    for (int t = gtid; t < ND*DIM; t += nth) {
        int c = t & 63;
        out[t] = gamma[c] * (g_y[t] - g_mean[c]) * g_rstd[c] + beta[c];
    }
}

// ---------------------------------------------------------------- host
static void compute_keys(u32& k1x, u32& k1y, u32& kLx, u32& kLy) {
    u32 a, b, c, d, e, f;
    threefry(0u, 42u, 0u, 0u, a, b);   // k1 = split(key(42))[0]
    k1x = a; k1y = b;
    threefry(0u, 42u, 0u, 1u, c, d);   // k2 = split(key(42))[1]
    threefry(c, d, 0u, 1u, e, f);      // split(k2)[1]
    kLx = e; kLy = f;
}

extern "C" void kernel_launch(void* const* d_in, const int* in_sizes, int n_in,
                              void* d_out, int out_size) {
    const float* HF       = (const float*)d_in[0];
    const float* X        = (const float*)d_in[1];
    const float* drug_emb = (const float*)d_in[2];
    const float* rel_emb  = (const float*)d_in[3];
    const float* tail_emb = (const float*)d_in[4];
    const float* W1       = (const float*)d_in[5];
    const float* b1       = (const float*)d_in[6];
    const float* W2       = (const float*)d_in[7];
    const float* b2       = (const float*)d_in[8];
    const float* Wc       = (const float*)d_in[9];
    const float* bc       = (const float*)d_in[10];
    const float* gamma    = (const float*)d_in[11];
    const float* beta     = (const float*)d_in[12];
    const int*   DKG      = (const int*)d_in[13];
    int E    = in_sizes[13] / 3;
    int hf_n = in_sizes[0];
    int x_n  = in_sizes[1];
    float* out = (float*)d_out;

    u32 k1x, k1y, kLx, kLy;
    compute_keys(k1x, k1y, kLx, kLy);

    cudaMemcpyAsync(out, HF, (size_t)hf_n * sizeof(float), cudaMemcpyDeviceToDevice, 0);
    cudaMemcpyAsync(out + hf_n + ND*DIM, X, (size_t)x_n * sizeof(float),
                    cudaMemcpyDeviceToDevice, 0);

    init_kernel<<<(ND + NTHR - 1)/NTHR + 1, NTHR>>>(W2, b2);
    mega_kernel<<<NBLK, NTHR>>>(DKG, drug_emb, rel_emb, tail_emb, W1, b1, Wc, bc,
                                gamma, beta, out + hf_n, E, k1x, k1y, kLx, kLy);
}

// round 3
// speedup vs baseline: 1.1474x; 1.0619x over previous
#include <cuda_runtime.h>
#include <stdint.h>

#define ND    10000
#define DIM   64
#define SS    16
#define EMAX  1000000
#define NBLK  296
#define NTHR  512
#define NWPB  16                 // warps per block
#define NWARP (NBLK*NWPB)
#define CHUNK 34                 // ceil(ND/NBLK)
#define KEYCAP 160               // per-warp smem key cache (deg ~ Poisson(100))

typedef unsigned int u32;
typedef unsigned long long u64;

// ---------------------------------------------------------------- threefry2x32
__host__ __device__ __forceinline__ void threefry(u32 k0, u32 k1, u32 x0, u32 x1,
                                                  u32& o0, u32& o1) {
#define TFR(a,b,r) { a += b; b = (b<<r)|(b>>(32-r)); b ^= a; }
    u32 ks2 = k0 ^ k1 ^ 0x1BD11BDAu;
    x0 += k0; x1 += k1;
    TFR(x0,x1,13); TFR(x0,x1,15); TFR(x0,x1,26); TFR(x0,x1,6);
    x0 += k1; x1 += ks2 + 1u;
    TFR(x0,x1,17); TFR(x0,x1,29); TFR(x0,x1,16); TFR(x0,x1,24);
    x0 += ks2; x1 += k0 + 2u;
    TFR(x0,x1,13); TFR(x0,x1,15); TFR(x0,x1,26); TFR(x0,x1,6);
    x0 += k0; x1 += k1 + 3u;
    TFR(x0,x1,17); TFR(x0,x1,29); TFR(x0,x1,16); TFR(x0,x1,24);
    x0 += k1; x1 += ks2 + 4u;
    TFR(x0,x1,13); TFR(x0,x1,15); TFR(x0,x1,26); TFR(x0,x1,6);
    x0 += ks2; x1 += k0 + 5u;
    o0 = x0; o1 = x1;
#undef TFR
}
__device__ __forceinline__ u32 rbits_stream(u32 kx, u32 ky, int i) {
    u32 a, b; threefry(kx, ky, 0u, (u32)i, a, b);
    return a ^ b;
}

// ---------------------------------------------------------------- scratch
__device__ int   g_deg[ND];
__device__ int   g_cursor[ND];
__device__ int   g_off[ND];
__device__ u64   g_key[EMAX];
__device__ int   g_bsum[NBLK];
__device__ int   g_boff[NBLK];
__device__ float g_neigh[ND*DIM];
__device__ float g_y[ND*DIM];
__device__ float g_psum[NBLK*DIM];
__device__ float g_psq[NBLK*DIM];
__device__ float g_mean[DIM];
__device__ float g_rstd[DIM];
__device__ float g_w2s[DIM];
__device__ float g_b2s;
__device__ u32   g_bar_count;
__device__ u32   g_bar_gen;

// ---------------------------------------------------------------- init kernel
__global__ void init_kernel() {
    int i = blockIdx.x * blockDim.x + threadIdx.x;
    if (i < ND) { g_deg[i] = 0; g_cursor[i] = 0; }
    if (i == ND) { g_bar_count = 0; g_bar_gen = 0; }
}

// ---------------------------------------------------------------- f32x2 helpers
__device__ __forceinline__ u64 pack2(float lo, float hi) {
    u64 r;
    asm("mov.b64 %0, {%1, %2};" : "=l"(r) : "f"(lo), "f"(hi));
    return r;
}
__device__ __forceinline__ void unpack2(u64 v, float& lo, float& hi) {
    asm("mov.b64 {%0, %1}, %2;" : "=f"(lo), "=f"(hi) : "l"(v));
}
__device__ __forceinline__ void fma2(u64& acc, u64 a, u64 b) {
    asm("fma.rn.f32x2 %0, %1, %2, %0;" : "+l"(acc) : "l"(a), "l"(b));
}

// ---------------------------------------------------------------- shared layout
// [0      .. 16384)  w1p  u64[2048]         (phase score)    | phase2: s_scan/s_b | phase7: Wcs+red | phase8: ss/qq
// [16384  .. 16640)  b1s  float[64]
// [16640  .. 16896)  w2ss float[64]
// [16896  .. 17920)  ssel int[NWPB*16]
// [17920  .. 38400)  wkeys u64[NWPB*KEYCAP]
#define SH_BYTES (38*1024 + 512)

__global__ void __launch_bounds__(NTHR, 2)
mega_kernel(const int* __restrict__ DKG,
            const float* __restrict__ drug_emb,
            const float* __restrict__ rel_emb,
            const float* __restrict__ tail_emb,
            const float* __restrict__ W1,
            const float* __restrict__ b1,
            const float* __restrict__ W2,
            const float* __restrict__ b2,
            const float* __restrict__ Wc,
            const float* __restrict__ bc,
            const float* __restrict__ gamma,
            const float* __restrict__ beta,
            float* __restrict__ out,
            int E, u32 k1x, u32 k1y, u32 kLx, u32 kLy) {
    __shared__ __align__(16) char sh_raw[SH_BYTES];
    __shared__ u32 s_gen;

    const int tid  = threadIdx.x;
    const int bid  = blockIdx.x;
    const int gtid = bid * NTHR + tid;
    const int nth  = NBLK * NTHR;
    const int lane = tid & 31;
    const int wid  = tid >> 5;

    if (tid == 0) s_gen = 0;

    // -------- grid barrier: atomic arrive, volatile-load poll --------
    auto gsync = [&]() {
        __syncthreads();
        if (tid == 0) {
            u32 target = s_gen + 1;
            __threadfence();
            u32 t = atomicAdd(&g_bar_count, 1u);
            if (t == (u32)NBLK - 1) {
                atomicExch(&g_bar_count, 0u);
                __threadfence();
                atomicExch(&g_bar_gen, target);
            } else {
                volatile u32* vg = &g_bar_gen;
                while (*vg < target) { }
            }
            __threadfence();
            s_gen = target;
        }
        __syncthreads();
    };

    // ============ phase 1: degree histogram (+ w2s by last block) ============
    if (bid == NBLK - 1) {
        if (tid < DIM) {
            float s = 0.f;
            for (int j = 0; j < DIM; j++) s += W2[tid*DIM + j];
            g_w2s[tid] = s;
        }
        if (tid == DIM) {
            float s = 0.f;
            for (int j = 0; j < DIM; j++) s += b2[j];
            g_b2s = s;
        }
    }
    for (int e = gtid; e < E; e += nth) {
        atomicAdd(&g_deg[DKG[3*e]], 1);
    }
    gsync();

    // ============ phase 2: exclusive scan of deg -> off ============
    {
        int* s_scan = (int*)sh_raw;            // 64 ints
        int* s_b    = (int*)(sh_raw + 1024);   // 512 ints
        const int d0 = bid * CHUNK;
        int myv = 0;
        if (tid < 64) s_scan[tid] = 0;
        __syncthreads();
        if (tid < CHUNK && d0 + tid < ND) { myv = g_deg[d0 + tid]; s_scan[tid] = myv; }
        __syncthreads();
        #pragma unroll
        for (int ofs = 1; ofs < 64; ofs <<= 1) {
            int v = (tid < 64 && tid >= ofs) ? s_scan[tid - ofs] : 0;
            __syncthreads();
            if (tid < 64) s_scan[tid] += v;
            __syncthreads();
        }
        if (tid == 0) g_bsum[bid] = s_scan[63];
        gsync();

        if (bid == 0) {
            s_b[tid] = (tid < NBLK) ? g_bsum[tid] : 0;
            __syncthreads();
            #pragma unroll
            for (int ofs = 1; ofs < NTHR; ofs <<= 1) {
                int v = (tid >= ofs) ? s_b[tid - ofs] : 0;
                __syncthreads();
                s_b[tid] += v;
                __syncthreads();
            }
            if (tid < NBLK) g_boff[tid] = tid ? s_b[tid - 1] : 0;
        }
        gsync();

        if (tid < CHUNK && d0 + tid < ND)
            g_off[d0 + tid] = g_boff[bid] + s_scan[tid] - myv;
    }
    gsync();

    // ============ phase 3: scatter (rank23|edge20) keys into CSR ============
    for (int e = gtid; e < E; e += nth) {
        int h = DKG[3*e];
        u32 bits = rbits_stream(k1x, k1y, e);
        u64 key = (((u64)(bits >> 9)) << 20) | (u32)e;
        int pos = g_off[h] + atomicAdd(&g_cursor[h], 1);
        g_key[pos] = key;
    }
    gsync();

    // ============ phase 4+5+6 fused: per-drug select top16 + score + aggregate ============
    {
        u64*   w1p   = (u64*)sh_raw;                         // 2048 u64
        float* b1s   = (float*)(sh_raw + 16384);
        float* w2ss  = (float*)(sh_raw + 16640);
        int*   ssel  = (int*)(sh_raw + 16896) + wid * 16;
        u64*   wkeys = (u64*)(sh_raw + 17920) + wid * KEYCAP;

        for (int i = tid; i < 64*32; i += NTHR) {
            int r = i >> 5, c = i & 31;
            w1p[i] = pack2(W1[r*DIM + c], W1[r*DIM + c + 32]);
        }
        if (tid < DIM)        b1s[tid] = b1[tid];
        else if (tid < 2*DIM) w2ss[tid - DIM] = g_w2s[tid - DIM];
        __syncthreads();
        const float b2s = g_b2s;

        for (int d = bid * NWPB + wid; d < ND; d += NWARP) {
            const int off  = g_off[d];
            const int degd = g_deg[d];
            const int cnt  = (degd < SS) ? degd : SS;

            if (cnt > 0) {
                // ---- selection: top-16 smallest keys, rank-ordered ----
                if (degd <= KEYCAP) {
                    for (int t = lane; t < degd; t += 32) wkeys[t] = g_key[off + t];
                    __syncwarp();
                    for (int t = lane; t < degd; t += 32) {
                        u64 k = wkeys[t];
                        int rank = 0;
                        for (int j = 0; j < degd; j++) rank += (wkeys[j] < k);
                        if (rank < SS) ssel[rank] = (int)(k & 0xFFFFFu);
                    }
                } else {
                    for (int t = lane; t < degd; t += 32) {
                        u64 k = g_key[off + t];
                        int rank = 0;
                        for (int j = 0; j < degd; j++) rank += (g_key[off + j] < k);
                        if (rank < SS) ssel[rank] = (int)(k & 0xFFFFFu);
                    }
                }
                __syncwarp();

                // ---- gather tail/rel for the selected units ----
                int tail = 0, rel = 0;
                if (lane < cnt) {
                    int e = ssel[lane];
                    tail = DKG[3*e + 1];
                    rel  = DKG[3*e + 2];
                }
                __syncwarp();

                const float de0 = drug_emb[d*DIM + lane];
                const float de1 = drug_emb[d*DIM + 32 + lane];
                const u64 binit = pack2(b1s[lane], b1s[lane + 32]);
                const float w20 = w2ss[lane], w21 = w2ss[lane + 32];

                float myscore = 0.f;
                for (int k = 0; k < cnt; k++) {
                    int relk = __shfl_sync(0xffffffffu, rel, k);
                    float h0 = de0 * rel_emb[relk*DIM + lane];
                    float h1 = de1 * rel_emb[relk*DIM + 32 + lane];
                    u64 acc = binit;
                    #pragma unroll
                    for (int i = 0; i < 32; i++) {
                        float v = __shfl_sync(0xffffffffu, h0, i);
                        fma2(acc, pack2(v, v), w1p[i*32 + lane]);
                    }
                    #pragma unroll
                    for (int i = 0; i < 32; i++) {
                        float v = __shfl_sync(0xffffffffu, h1, i);
                        fma2(acc, pack2(v, v), w1p[(i + 32)*32 + lane]);
                    }
                    float a0, a1;
                    unpack2(acc, a0, a1);
                    float s0 = 1.f / (1.f + __expf(-a0));
                    float s1 = 1.f / (1.f + __expf(-a1));
                    float p = s0 * w20 + s1 * w21;
                    #pragma unroll
                    for (int o = 16; o; o >>= 1) p += __shfl_xor_sync(0xffffffffu, p, o);
                    if (lane == k) myscore = p + b2s;
                }

                // ---- aggregation (rank order, then extras) ----
                float acc0 = 0.f, acc1 = 0.f;
                for (int k = 0; k < cnt; k++) {
                    float sc = __shfl_sync(0xffffffffu, myscore, k);
                    int   t  = __shfl_sync(0xffffffffu, tail, k);
                    acc0 = fmaf(sc, tail_emb[t*DIM + lane], acc0);
                    acc1 = fmaf(sc, tail_emb[t*DIM + 32 + lane], acc1);
                }
                if (degd < SS) {
                    for (int s = 0; s < SS - degd; s++) {
                        u32 bits = rbits_stream(kLx, kLy, d*SS + s);
                        int idx = (int)((bits % 2147483647u) % (u32)degd);
                        float sc = __shfl_sync(0xffffffffu, myscore, idx);
                        int   t  = __shfl_sync(0xffffffffu, tail, idx);
                        acc0 = fmaf(sc, tail_emb[t*DIM + lane], acc0);
                        acc1 = fmaf(sc, tail_emb[t*DIM + 32 + lane], acc1);
                    }
                }
                g_neigh[d*DIM + lane]      = acc0;
                g_neigh[d*DIM + 32 + lane] = acc1;
            } else {
                g_neigh[d*DIM + lane]      = 0.f;
                g_neigh[d*DIM + 32 + lane] = 0.f;
            }
        }
    }
    gsync();

    // ============ phase 7: y = [drug_emb, neigh] @ Wc + bc, partial BN stats ============
    {
        float* wcs = (float*)sh_raw;                 // 8192 floats = 32KB
        float* red = (float*)(sh_raw + 32*1024);     // 512 floats
        for (int i = tid; i < 2*DIM*DIM; i += NTHR) wcs[i] = Wc[i];
        __syncthreads();
        const int sub = tid >> 6;       // 0..7
        const int col = tid & 63;
        float accS = 0.f, accQ = 0.f;
        const float bcc = bc[col];
        for (int r8 = bid; r8 < ND/8; r8 += NBLK) {
            int row = r8*8 + sub;
            const float* de = drug_emb + row*DIM;
            const float* ne = g_neigh + row*DIM;
            float acc = bcc;
            #pragma unroll
            for (int i = 0; i < DIM; i++) acc = fmaf(de[i], wcs[i*DIM + col], acc);
            #pragma unroll
            for (int i = 0; i < DIM; i++) acc = fmaf(ne[i], wcs[(DIM + i)*DIM + col], acc);
            g_y[row*DIM + col] = acc;
            accS += acc;
            accQ += acc * acc;
        }
        red[tid] = accS;
        __syncthreads();
        if (tid < 64) {
            float s = 0.f;
            #pragma unroll
            for (int p = 0; p < 8; p++) s += red[p*64 + col];
            g_psum[bid*DIM + col] = s;
        }
        __syncthreads();
        red[tid] = accQ;
        __syncthreads();
        if (tid < 64) {
            float q = 0.f;
            #pragma unroll
            for (int p = 0; p < 8; p++) q += red[p*64 + col];
            g_psq[bid*DIM + col] = q;
        }
    }
    gsync();

    // ============ phase 8: final BN stats (block 0) ============
    if (bid == 0) {
        float* ss = (float*)sh_raw;
        float* qq = (float*)(sh_raw + 2048);
        const int col = tid & 63, part = tid >> 6;
        float s = 0.f, q = 0.f;
        for (int b = part; b < NBLK; b += 8) { s += g_psum[b*DIM + col]; q += g_psq[b*DIM + col]; }
        ss[tid] = s; qq[tid] = q;
        __syncthreads();
        if (tid < 64) {
            float S = 0.f, Q = 0.f;
            #pragma unroll
            for (int p = 0; p < 8; p++) { S += ss[p*64 + col]; Q += qq[p*64 + col]; }
            float mean = S / (float)ND;
            float var  = Q / (float)ND - mean * mean;
            g_mean[col] = mean;
            g_rstd[col] = rsqrtf(var + 1e-5f);
        }
    }
    gsync();

    // ============ phase 9: normalize + write out ============
    for (int t = gtid; t < ND*DIM; t += nth) {
        int c = t & 63;
        out[t] = gamma[c] * (g_y[t] - g_mean[c]) * g_rstd[c] + beta[c];
    }
}

// ---------------------------------------------------------------- host
static void compute_keys(u32& k1x, u32& k1y, u32& kLx, u32& kLy) {
    u32 a, b, c, d, e, f;
    threefry(0u, 42u, 0u, 0u, a, b);   // k1 = split(key(42))[0]
    k1x = a; k1y = b;
    threefry(0u, 42u, 0u, 1u, c, d);   // k2 = split(key(42))[1]
    threefry(c, d, 0u, 1u, e, f);      // split(k2)[1]
    kLx = e; kLy = f;
}

extern "C" void kernel_launch(void* const* d_in, const int* in_sizes, int n_in,
                              void* d_out, int out_size) {
    const float* HF       = (const float*)d_in[0];
    const float* X        = (const float*)d_in[1];
    const float* drug_emb = (const float*)d_in[2];
    const float* rel_emb  = (const float*)d_in[3];
    const float* tail_emb = (const float*)d_in[4];
    const float* W1       = (const float*)d_in[5];
    const float* b1       = (const float*)d_in[6];
    const float* W2       = (const float*)d_in[7];
    const float* b2       = (const float*)d_in[8];
    const float* Wc       = (const float*)d_in[9];
    const float* bc       = (const float*)d_in[10];
    const float* gamma    = (const float*)d_in[11];
    const float* beta     = (const float*)d_in[12];
    const int*   DKG      = (const int*)d_in[13];
    int E    = in_sizes[13] / 3;
    int hf_n = in_sizes[0];
    int x_n  = in_sizes[1];
    float* out = (float*)d_out;

    u32 k1x, k1y, kLx, kLy;
    compute_keys(k1x, k1y, kLx, kLy);

    cudaMemcpyAsync(out, HF, (size_t)hf_n * sizeof(float), cudaMemcpyDeviceToDevice, 0);
    cudaMemcpyAsync(out + hf_n + ND*DIM, X, (size_t)x_n * sizeof(float),
                    cudaMemcpyDeviceToDevice, 0);

    init_kernel<<<(ND + 256)/256, 256>>>();
    mega_kernel<<<NBLK, NTHR>>>(DKG, drug_emb, rel_emb, tail_emb, W1, b1, W2, b2,
                                Wc, bc, gamma, beta, out + hf_n,
                                E, k1x, k1y, kLx, kLy);
}